// round 3
// baseline (speedup 1.0000x reference)
#include <cuda_runtime.h>

#define PI_F 3.14159265358979323846f

// ---------------------------------------------------------------------------
// Fixed shapes:
//   features      [8192, 4096] f32
//   projection_w  [16, 4096]   f32
//   projection_b  [16]         f32
//   vqc_weights   [24, 16, 3]  f32
//   linear_w      [16, 512]    f32
//   linear_b      [512]        f32
//   out           [8192, 512]  f32
// ---------------------------------------------------------------------------
constexpr int B_ROWS  = 8192;
constexpr int D_DIM   = 4096;
constexpr int Q_DIM   = 16;
constexpr int L_LAY   = 24;
constexpr int C_DIM   = 512;

constexpr int ROWS_PER_BLOCK = 32;
constexpr int THREADS        = 128;
constexpr int NUM_BLOCKS     = B_ROWS / ROWS_PER_BLOCK;   // 256 -> 2 blocks/SM

// dynamic smem (floats):
//   scratch: 512 states x 16 k-slices = 8192 floats (32 KB), reused as zbuf
//   trig:    24*16*6 = 2304 floats (9 KB)
// total 41984 B < 48 KB default -> no cudaFuncSetAttribute needed.
constexpr int SCRATCH_FLOATS = ROWS_PER_BLOCK * Q_DIM * 16;     // 8192
constexpr int TRIG_FLOATS    = L_LAY * Q_DIM * 6;               // 2304
constexpr int SMEM_BYTES     = (SCRATCH_FLOATS + TRIG_FLOATS) * 4;

// ---- packed fp32x2 helpers (B300 double-rate fp32 path) -------------------
__device__ __forceinline__ unsigned long long ffma2(unsigned long long a,
                                                    unsigned long long b,
                                                    unsigned long long c) {
    unsigned long long d;
    asm("fma.rn.f32x2 %0, %1, %2, %3;" : "=l"(d) : "l"(a), "l"(b), "l"(c));
    return d;
}
__device__ __forceinline__ float f2lo(unsigned long long v) {
    return __uint_as_float((unsigned)(v & 0xffffffffull));
}
__device__ __forceinline__ float f2hi(unsigned long long v) {
    return __uint_as_float((unsigned)(v >> 32));
}
__device__ __forceinline__ unsigned long long packf2(float lo, float hi) {
    unsigned long long d;
    asm("mov.b64 %0, {%1, %2};" : "=l"(d)
        : "r"(__float_as_uint(lo)), "r"(__float_as_uint(hi)));
    return d;
}

__global__ void __launch_bounds__(THREADS, 2)
vqc_router_fused(const float* __restrict__ features,
                 const float* __restrict__ pw,
                 const float* __restrict__ pb,
                 const float* __restrict__ vqcw,
                 const float* __restrict__ lw,
                 const float* __restrict__ lb,
                 float* __restrict__ out)
{
    extern __shared__ float smem[];
    float* scratch = smem;                    // 8192 floats (reused as zbuf)
    float* trig    = smem + SCRATCH_FLOATS;   // 2304 floats

    const int tid  = threadIdx.x;
    const int lane = tid & 31;
    const int warp = tid >> 5;                // 0..3
    const int s    = lane & 15;               // k-slice id within 64-k span
    const int rg   = warp * 2 + (lane >> 4);  // row-group 0..7 (4 rows each)
    const int row0 = blockIdx.x * ROWS_PER_BLOCK + rg * 4;

    // ---- precompute trig of VQC weights: [l][q][6] = cp,sp,ct,st,co,so ----
    for (int i = tid; i < L_LAY * Q_DIM * 3; i += THREADS) {
        float sv, cv;
        sincosf(vqcw[i], &sv, &cv);
        int l   = i / (Q_DIM * 3);
        int rem = i - l * (Q_DIM * 3);
        int q   = rem / 3;
        int p   = rem - q * 3;
        trig[(l * Q_DIM + q) * 6 + 2 * p + 0] = cv;
        trig[(l * Q_DIM + q) * 6 + 2 * p + 1] = sv;
    }

    // ---- GEMM1: 4 rows x 16 q per thread, 16-way k-split within half-warp -
    // thread's k set: { span*64 + 4*s .. +3 } for span = 0..63
    unsigned long long acc[4][16];
#pragma unroll
    for (int r = 0; r < 4; r++)
#pragma unroll
        for (int q = 0; q < 16; q++) acc[r][q] = 0ull;

    const float* fb = features + (size_t)row0 * D_DIM + s * 4;
    const float* wb = pw + s * 4;

    ulonglong2 fcur[4], fnxt[4];
#pragma unroll
    for (int r = 0; r < 4; r++)
        fcur[r] = *reinterpret_cast<const ulonglong2*>(fb + (size_t)r * D_DIM);

    for (int sp = 0; sp < 64; sp++) {
        const int koff = sp * 64;
        if (sp + 1 < 64) {
#pragma unroll
            for (int r = 0; r < 4; r++)
                fnxt[r] = *reinterpret_cast<const ulonglong2*>(
                    fb + (size_t)r * D_DIM + koff + 64);
        }
#pragma unroll
        for (int q = 0; q < 16; q++) {
            ulonglong2 wv = *reinterpret_cast<const ulonglong2*>(
                wb + (size_t)q * D_DIM + koff);
#pragma unroll
            for (int r = 0; r < 4; r++) {
                acc[r][q] = ffma2(fcur[r].x, wv.x, acc[r][q]);
                acc[r][q] = ffma2(fcur[r].y, wv.y, acc[r][q]);
            }
        }
#pragma unroll
        for (int r = 0; r < 4; r++) fcur[r] = fnxt[r];
    }

    // ---- write k-split partials: scratch[state][s], state = row_local*16+q
#pragma unroll
    for (int j = 0; j < 4; j++)
#pragma unroll
        for (int q = 0; q < 16; q++)
            scratch[((rg * 4 + j) * Q_DIM + q) * 16 + s] =
                f2lo(acc[j][q]) + f2hi(acc[j][q]);

    __syncthreads();

    // ---- reduce 16 partials, tanh, VQC (4 states per thread) --------------
    float zout[4];
#pragma unroll
    for (int i = 0; i < 4; i++) {
        const int idx = tid * 4 + i;          // 0..511
        const int q   = idx & 15;
        const float4* p4 = reinterpret_cast<const float4*>(scratch + idx * 16);
        float4 a0 = p4[0], a1 = p4[1], a2 = p4[2], a3 = p4[3];
        float p = ((a0.x + a0.y) + (a0.z + a0.w))
                + ((a1.x + a1.y) + (a1.z + a1.w))
                + ((a2.x + a2.y) + (a2.z + a2.w))
                + ((a3.x + a3.y) + (a3.z + a3.w)) + pb[q];

        float ang = PI_F * tanhf(p);
        float x, z;
        sincosf(ang, &x, &z);                 // x = sin, z = cos
        float y = 0.0f;
#pragma unroll
        for (int l = 0; l < L_LAY; l++) {
            const float* t6 = trig + (l * Q_DIM + q) * 6;
            float cp = t6[0], spv = t6[1];
            float ct = t6[2], st  = t6[3];
            float co = t6[4], so  = t6[5];
            float x1 = x * cp - y * spv;
            float y1 = x * spv + y * cp;
            float x2 = x1 * ct + z * st;
            float z2 = -x1 * st + z * ct;
            x = x2 * co - y1 * so;
            y = x2 * so + y1 * co;
            z = z2;
        }
        zout[i] = z;
    }
    __syncthreads();                          // everyone done reading scratch

    // reuse scratch as zbuf[32][16]
#pragma unroll
    for (int i = 0; i < 4; i++) scratch[tid * 4 + i] = zout[i];
    __syncthreads();

    // ---- GEMM2: out[32][512] = z[32][16] @ lw[16][512] + lb ---------------
    const int c0 = tid * 4;                   // four output cols per thread
    ulonglong2 wreg[16];
#pragma unroll
    for (int q = 0; q < 16; q++)
        wreg[q] = *reinterpret_cast<const ulonglong2*>(
            lw + (size_t)q * C_DIM + c0);
    const ulonglong2 bias4 =
        *reinterpret_cast<const ulonglong2*>(lb + c0);

    float* obase = out + (size_t)(blockIdx.x * ROWS_PER_BLOCK) * C_DIM + c0;
    for (int r = 0; r < ROWS_PER_BLOCK; r++) {
        ulonglong2 a = bias4;
#pragma unroll
        for (int q = 0; q < 16; q++) {
            float zv = scratch[r * Q_DIM + q];
            unsigned long long zz = packf2(zv, zv);
            a.x = ffma2(zz, wreg[q].x, a.x);
            a.y = ffma2(zz, wreg[q].y, a.y);
        }
        *reinterpret_cast<ulonglong2*>(obase + (size_t)r * C_DIM) = a;
    }
}

extern "C" void kernel_launch(void* const* d_in, const int* in_sizes, int n_in,
                              void* d_out, int out_size) {
    const float* features = (const float*)d_in[0];
    const float* pw       = (const float*)d_in[1];
    const float* pb       = (const float*)d_in[2];
    const float* vqcw     = (const float*)d_in[3];
    const float* lw       = (const float*)d_in[4];
    const float* lb       = (const float*)d_in[5];
    float* out            = (float*)d_out;

    vqc_router_fused<<<NUM_BLOCKS, THREADS, SMEM_BYTES>>>(
        features, pw, pb, vqcw, lw, lb, out);
}